// round 16
// baseline (speedup 1.0000x reference)
#include <cuda_runtime.h>
#include <cuda_bf16.h>
#include <cstdint>

// Problem constants (fixed by setup_inputs)
#define BATCH   8
#define S_LEN   1024
#define D_MODEL 1024
#define NH      16
#define DH      64
#define M_ROWS  (BATCH * S_LEN)   // 8192
#define DD      (D_MODEL * D_MODEL)
#define DU      (D_MODEL / 2)     // u32 (bf16x2) per row
#define MU      (M_ROWS * DU)     // u32 per activation slab
#define SU2     (S_LEN / 2)       // key-pairs per sequence

// ---------------------------------------------------------------------------
// Scratch (device globals — no allocations allowed)
// ---------------------------------------------------------------------------
__device__ uint32_t g_Ahp[3 * MU];
__device__ uint32_t g_Alp[3 * MU];
__device__ uint32_t g_Whp[4 * DD / 2];
__device__ uint32_t g_Wlp[4 * DD / 2];
__device__ uint32_t g_Qh[MU], g_Ql[MU];
__device__ uint32_t g_Kh[MU], g_Kl[MU];
__device__ uint32_t g_VtH[MU], g_VtL[MU];   // V transposed per (b,h): [dh][key-pair]
__device__ uint32_t g_Oh[MU], g_Ol[MU];

// ---------------------------------------------------------------------------
// bf16 helpers (3xBF16: x = h + l; keep ah*bh + ah*bl + al*bh)
// ---------------------------------------------------------------------------
__device__ __forceinline__ uint32_t bpack(float x0, float x1) {
    __nv_bfloat162 t = __floats2bfloat162_rn(x0, x1);   // x0 -> low half
    return *reinterpret_cast<uint32_t*>(&t);
}
__device__ __forceinline__ void bsplit2(float x0, float x1, uint32_t& ph, uint32_t& pl) {
    const float h0 = __bfloat162float(__float2bfloat16(x0));
    const float h1 = __bfloat162float(__float2bfloat16(x1));
    ph = bpack(h0, h1);
    pl = bpack(x0 - h0, x1 - h1);
}
__device__ __forceinline__ void mma_bf16(float* c, const uint32_t* a, uint32_t b0, uint32_t b1) {
    asm volatile(
        "mma.sync.aligned.m16n8k16.row.col.f32.bf16.bf16.f32 "
        "{%0,%1,%2,%3}, {%4,%5,%6,%7}, {%8,%9}, {%0,%1,%2,%3};\n"
        : "+f"(c[0]), "+f"(c[1]), "+f"(c[2]), "+f"(c[3])
        : "r"(a[0]), "r"(a[1]), "r"(a[2]), "r"(a[3]), "r"(b0), "r"(b1));
}

// ---------------------------------------------------------------------------
// cp.async helpers
// ---------------------------------------------------------------------------
__device__ __forceinline__ void cpa16(uint32_t smaddr, const void* gptr) {
    asm volatile("cp.async.cg.shared.global [%0], [%1], 16;\n"
                 :: "r"(smaddr), "l"(gptr));
}
#define CP_COMMIT() asm volatile("cp.async.commit_group;\n" ::: "memory")
#define CP_WAIT1()  asm volatile("cp.async.wait_group 1;\n" ::: "memory")
#define CP_WAIT0()  asm volatile("cp.async.wait_group 0;\n" ::: "memory")

// ---------------------------------------------------------------------------
// Pre-split kernels (fp32 -> packed bf16x2 hi/lo)
// ---------------------------------------------------------------------------
__global__ void split_weights_kernel(
    const float* __restrict__ W0, const float* __restrict__ W1,
    const float* __restrict__ W2, const float* __restrict__ W3,
    uint32_t* __restrict__ Hp, uint32_t* __restrict__ Lp)
{
    const int z = blockIdx.y;
    const float* W = (z == 0) ? W0 : (z == 1) ? W1 : (z == 2) ? W2 : W3;
    const size_t fi = ((size_t)blockIdx.x * 256 + threadIdx.x) * 4;
    const size_t ui = (size_t)z * (DD / 2) + fi / 2;
    float4 x = *(const float4*)(W + fi);
    uint2 h2, l2;
    bsplit2(x.x, x.y, h2.x, l2.x);
    bsplit2(x.z, x.w, h2.y, l2.y);
    *(uint2*)(Hp + ui) = h2;
    *(uint2*)(Lp + ui) = l2;
}

__global__ void split_acts_kernel(
    const float* __restrict__ X0, const float* __restrict__ X1,
    const float* __restrict__ X2,
    uint32_t* __restrict__ Hp, uint32_t* __restrict__ Lp)
{
    const int z = blockIdx.y;
    const float* X = (z == 0) ? X0 : (z == 1) ? X1 : X2;
    const size_t fi = ((size_t)blockIdx.x * 256 + threadIdx.x) * 4;
    const size_t ui = (size_t)z * MU + fi / 2;
    float4 x = *(const float4*)(X + fi);
    uint2 h2, l2;
    bsplit2(x.x, x.y, h2.x, l2.x);
    bsplit2(x.z, x.w, h2.y, l2.y);
    *(uint2*)(Hp + ui) = h2;
    *(uint2*)(Lp + ui) = l2;
}

// ---------------------------------------------------------------------------
// GEMM v10:  C = A @ W^T + bias, bf16x3, cp.async 2-stage.
// CTA tile 256x128, 8 warps as 4(M) x 2(N), warp tile 64x64 (4x8 m16n8k16
// accumulators = 32 independent chains/warp; LDS:mma = 64:96 per k16-pair).
// Same stride-20 conflict-free smem layout and per-acc term order as before
// (bit-identical numerics).
// ---------------------------------------------------------------------------
#define GBK 32
#define GKU 16
#define GLD 20
#define AT_U32g (256 * GLD)                    // A tile (5120 u32)
#define BT_U32g (128 * GLD)                    // B tile (2560 u32)
#define STAGEg (2 * AT_U32g + 2 * BT_U32g)     // 15360 u32
#define G10_SMEM (2 * STAGEg * 4)              // 122880 bytes

__global__ void __launch_bounds__(256, 1) gemm10_bf16(
    const uint32_t* __restrict__ Ahp, const uint32_t* __restrict__ Alp,
    const uint32_t* __restrict__ Whp, const uint32_t* __restrict__ Wlp,
    const float* __restrict__ b0, const float* __restrict__ b1, const float* __restrict__ b2,
    uint32_t* __restrict__ QhO, uint32_t* __restrict__ QlO,
    uint32_t* __restrict__ KhO, uint32_t* __restrict__ KlO,
    uint32_t* __restrict__ VtHO, uint32_t* __restrict__ VtLO,
    float* __restrict__ Cout,
    int widx0, int outproj)
{
    extern __shared__ uint32_t smu[];

    const int z = blockIdx.z;
    const float* bias = (z == 0) ? b0 : (z == 1) ? b1 : b2;
    const uint32_t* Ah = Ahp + (size_t)z * MU;
    const uint32_t* Al = Alp + (size_t)z * MU;
    const uint32_t* Bh = Whp + (size_t)(widx0 + z) * (DD / 2);
    const uint32_t* Bl = Wlp + (size_t)(widx0 + z) * (DD / 2);

    const int tid  = threadIdx.x;
    const int lane = tid & 31;
    const int warp = tid >> 5;
    const int wm = warp & 3;           // m0 = wm*64
    const int wn = warp >> 2;          // n0 = wn*64
    const int gi = lane >> 2;
    const int t4 = lane & 3;

    const int bm = blockIdx.y * 256;
    const int bn = blockIdx.x * 128;

    // loaders: A row = tid (16 u32); B row = tid>>1, half = (tid&1)*8
    const uint32_t* Ahg = Ah + (size_t)(bm + tid) * DU;
    const uint32_t* Alg = Al + (size_t)(bm + tid) * DU;
    const int brow = tid >> 1;
    const int buc  = (tid & 1) * 8;
    const uint32_t* Bhg = Bh + (size_t)(bn + brow) * DU + buc;
    const uint32_t* Blg = Bl + (size_t)(bn + brow) * DU + buc;

    const uint32_t smbase = (uint32_t)__cvta_generic_to_shared(smu);
    const uint32_t aoff = (uint32_t)(tid * GLD) * 4;
    const uint32_t boff = (uint32_t)(brow * GLD + buc) * 4;

    float acc[4][8][4];
    #pragma unroll
    for (int mt = 0; mt < 4; mt++)
        #pragma unroll
        for (int nt = 0; nt < 8; nt++)
            #pragma unroll
            for (int i = 0; i < 4; i++) acc[mt][nt][i] = 0.0f;

    auto load_stage = [&](int st, int k0) {
        const int ku = k0 >> 1;
        const uint32_t sb = smbase + (uint32_t)st * (STAGEg * 4);
        #pragma unroll
        for (int c = 0; c < 4; c++) {
            cpa16(sb + aoff + c * 16,                  Ahg + ku + c * 4);
            cpa16(sb + AT_U32g * 4 + aoff + c * 16,    Alg + ku + c * 4);
        }
        cpa16(sb + 2 * AT_U32g * 4 + boff,                       Bhg + ku);
        cpa16(sb + 2 * AT_U32g * 4 + boff + 16,                  Bhg + ku + 4);
        cpa16(sb + (2 * AT_U32g + BT_U32g) * 4 + boff,           Blg + ku);
        cpa16(sb + (2 * AT_U32g + BT_U32g) * 4 + boff + 16,      Blg + ku + 4);
    };

    const int ntiles = D_MODEL / GBK;
    load_stage(0, 0);
    CP_COMMIT();
    load_stage(1, GBK);
    CP_COMMIT();

    for (int i = 0; i < ntiles; i++) {
        if (i + 1 < ntiles) CP_WAIT1(); else CP_WAIT0();
        __syncthreads();

        const uint32_t* S   = smu + (i & 1) * STAGEg;
        const uint32_t* Ash = S;
        const uint32_t* Asl = S + AT_U32g;
        const uint32_t* Bsh = S + 2 * AT_U32g;
        const uint32_t* Bsl = S + 2 * AT_U32g + BT_U32g;

        #pragma unroll
        for (int kk = 0; kk < GKU; kk += 8) {
            uint32_t ah[4][4], al[4][4];
            #pragma unroll
            for (int mt = 0; mt < 4; mt++) {
                const int r = wm * 64 + mt * 16 + gi;
                ah[mt][0] = Ash[r * GLD + kk + t4];
                al[mt][0] = Asl[r * GLD + kk + t4];
                ah[mt][1] = Ash[(r + 8) * GLD + kk + t4];
                al[mt][1] = Asl[(r + 8) * GLD + kk + t4];
                ah[mt][2] = Ash[r * GLD + kk + t4 + 4];
                al[mt][2] = Asl[r * GLD + kk + t4 + 4];
                ah[mt][3] = Ash[(r + 8) * GLD + kk + t4 + 4];
                al[mt][3] = Asl[(r + 8) * GLD + kk + t4 + 4];
            }
            #pragma unroll
            for (int nt = 0; nt < 8; nt++) {
                const int rb = wn * 64 + nt * 8 + gi;
                const uint32_t bh0 = Bsh[rb * GLD + kk + t4];
                const uint32_t bh1 = Bsh[rb * GLD + kk + t4 + 4];
                const uint32_t bl0 = Bsl[rb * GLD + kk + t4];
                const uint32_t bl1 = Bsl[rb * GLD + kk + t4 + 4];
                #pragma unroll
                for (int mt = 0; mt < 4; mt++) {
                    mma_bf16(acc[mt][nt], al[mt], bh0, bh1);
                    mma_bf16(acc[mt][nt], ah[mt], bl0, bl1);
                    mma_bf16(acc[mt][nt], ah[mt], bh0, bh1);
                }
            }
        }

        __syncthreads();
        if (i + 2 < ntiles) {
            load_stage(i & 1, (i + 2) * GBK);
            CP_COMMIT();
        }
    }

    // ---------------- epilogue ----------------
    if (outproj) {
        #pragma unroll
        for (int nt = 0; nt < 8; nt++) {
            const int col = bn + wn * 64 + nt * 8 + 2 * t4;
            const float2 bb = *(const float2*)(bias + col);
            #pragma unroll
            for (int mt = 0; mt < 4; mt++) {
                const int row0 = bm + wm * 64 + mt * 16 + gi;
                float2 o0, o1;
                o0.x = acc[mt][nt][0] + bb.x; o0.y = acc[mt][nt][1] + bb.y;
                o1.x = acc[mt][nt][2] + bb.x; o1.y = acc[mt][nt][3] + bb.y;
                *(float2*)(Cout + (size_t)row0 * D_MODEL + col)       = o0;
                *(float2*)(Cout + (size_t)(row0 + 8) * D_MODEL + col) = o1;
            }
        }
    } else if (z < 2) {
        uint32_t* Ho = (z == 0) ? QhO : KhO;
        uint32_t* Lo = (z == 0) ? QlO : KlO;
        #pragma unroll
        for (int nt = 0; nt < 8; nt++) {
            const int col  = bn + wn * 64 + nt * 8 + 2 * t4;
            const int colu = col >> 1;
            const float2 bb = *(const float2*)(bias + col);
            #pragma unroll
            for (int mt = 0; mt < 4; mt++) {
                const int row0 = bm + wm * 64 + mt * 16 + gi;
                uint32_t ph, pl;
                bsplit2(acc[mt][nt][0] + bb.x, acc[mt][nt][1] + bb.y, ph, pl);
                Ho[(size_t)row0 * DU + colu] = ph;
                Lo[(size_t)row0 * DU + colu] = pl;
                bsplit2(acc[mt][nt][2] + bb.x, acc[mt][nt][3] + bb.y, ph, pl);
                Ho[(size_t)(row0 + 8) * DU + colu] = ph;
                Lo[(size_t)(row0 + 8) * DU + colu] = pl;
            }
        }
    } else {
        // V: transposed packed per (b,h): [dh][key-pair]
        #pragma unroll
        for (int nt = 0; nt < 8; nt++) {
            const int cg = bn + wn * 64 + nt * 8 + 2 * t4;
            const float2 bb = *(const float2*)(bias + cg);
            #pragma unroll
            for (int mt = 0; mt < 4; mt++) {
                const int r = bm + wm * 64 + mt * 16 + gi;
                const float c0 = acc[mt][nt][0] + bb.x;
                const float c1 = acc[mt][nt][1] + bb.y;
                const float c2 = acc[mt][nt][2] + bb.x;
                const float c3 = acc[mt][nt][3] + bb.y;
                const float p0 = __shfl_xor_sync(0xffffffffu, c0, 4);
                const float p1 = __shfl_xor_sync(0xffffffffu, c1, 4);
                const float p2 = __shfl_xor_sync(0xffffffffu, c2, 4);
                const float p3 = __shfl_xor_sync(0xffffffffu, c3, 4);
                uint32_t ph, pl;
                if ((gi & 1) == 0) {
                    const int bb_ = r >> 10, s = r & 1023;
                    const int h_ = cg >> 6, dh = cg & 63;
                    const size_t plane = ((size_t)(bb_ * NH + h_) * DH + dh) * SU2;
                    bsplit2(c0, p0, ph, pl);
                    VtHO[plane + (s >> 1)] = ph;
                    VtLO[plane + (s >> 1)] = pl;
                    bsplit2(c2, p2, ph, pl);
                    VtHO[plane + (s >> 1) + 4] = ph;
                    VtLO[plane + (s >> 1) + 4] = pl;
                } else {
                    const int rr = r - 1;
                    const int bb_ = rr >> 10, s = rr & 1023;
                    const int h_ = (cg + 1) >> 6, dh = (cg + 1) & 63;
                    const size_t plane = ((size_t)(bb_ * NH + h_) * DH + dh) * SU2;
                    bsplit2(p1, c1, ph, pl);
                    VtHO[plane + (s >> 1)] = ph;
                    VtLO[plane + (s >> 1)] = pl;
                    bsplit2(p3, c3, ph, pl);
                    VtHO[plane + (s >> 1) + 4] = ph;
                    VtLO[plane + (s >> 1) + 4] = pl;
                }
            }
        }
    }
}

// ---------------------------------------------------------------------------
// Flash attention (round-13 exact, measured 247.7us): bf16x3, pre-packed
// operands, cp.async 2-stage, register-direct P fragments.
// ---------------------------------------------------------------------------
#define A2_LDK 36
#define A2_TILE (64 * A2_LDK)
#define A2_STAGE (4 * A2_TILE)
#define A2_MSK (2 * A2_STAGE)
#define A2_SMEM ((A2_MSK + 32) * 4)

__global__ void __launch_bounds__(256, 1) attn_bf16_kernel(
    const uint32_t* __restrict__ Qh, const uint32_t* __restrict__ Ql,
    const uint32_t* __restrict__ Kh, const uint32_t* __restrict__ Kl,
    const uint32_t* __restrict__ VtH, const uint32_t* __restrict__ VtL,
    const unsigned char* __restrict__ kpm,
    uint32_t* __restrict__ Oh, uint32_t* __restrict__ Ol)
{
    extern __shared__ uint32_t su[];

    const int b   = blockIdx.z;
    const int h   = blockIdx.y;
    const int qt  = gridDim.x - 1 - blockIdx.x;   // heavy tiles first
    const int tid = threadIdx.x;
    const int w    = tid >> 5;
    const int lane = tid & 31;
    const int gi = lane >> 2;
    const int t4 = lane & 3;

    const int q0   = qt * 128;
    const int row0 = q0 + w * 16 + gi;

    const float scale = 0.125f;
    const float NEG = -1e30f;

    uint32_t qh[4][4], ql[4][4];
    {
        const uint32_t* q0h = Qh + (size_t)(b * S_LEN + row0) * DU + h * 32;
        const uint32_t* q1h = q0h + 8 * DU;
        const uint32_t* q0l = Ql + (size_t)(b * S_LEN + row0) * DU + h * 32;
        const uint32_t* q1l = q0l + 8 * DU;
        #pragma unroll
        for (int kc = 0; kc < 4; kc++) {
            qh[kc][0] = q0h[kc * 8 + t4];
            qh[kc][1] = q1h[kc * 8 + t4];
            qh[kc][2] = q0h[kc * 8 + t4 + 4];
            qh[kc][3] = q1h[kc * 8 + t4 + 4];
            ql[kc][0] = q0l[kc * 8 + t4];
            ql[kc][1] = q1l[kc * 8 + t4];
            ql[kc][2] = q0l[kc * 8 + t4 + 4];
            ql[kc][3] = q1l[kc * 8 + t4 + 4];
        }
    }

    float oc[8][4];
    #pragma unroll
    for (int nt = 0; nt < 8; nt++)
        #pragma unroll
        for (int i = 0; i < 4; i++) oc[nt][i] = 0.0f;
    float m0 = NEG, m1 = NEG, l0 = 0.0f, l1 = 0.0f;

    const int ldr = tid >> 2;
    const int seg = tid & 3;
    const uint32_t smbase = (uint32_t)__cvta_generic_to_shared(su);
    const uint32_t dsto = (uint32_t)(ldr * A2_LDK + seg * 8) * 4;

    const uint32_t* khg = Kh + (size_t)(b * S_LEN + ldr) * DU + h * 32 + seg * 8;
    const uint32_t* klg = Kl + (size_t)(b * S_LEN + ldr) * DU + h * 32 + seg * 8;
    const uint32_t* vhg = VtH + ((size_t)(b * NH + h) * DH + ldr) * SU2 + seg * 8;
    const uint32_t* vlg = VtL + ((size_t)(b * NH + h) * DH + ldr) * SU2 + seg * 8;
    const size_t kstep = (size_t)DU;

    auto load_tile = [&](int st, int kt) {
        const int k0 = kt * 64;
        const uint32_t sb = smbase + (uint32_t)st * (A2_STAGE * 4) + dsto;
        cpa16(sb,                     khg + (size_t)k0 * kstep);
        cpa16(sb + 16,                khg + (size_t)k0 * kstep + 4);
        cpa16(sb + A2_TILE * 4,       klg + (size_t)k0 * kstep);
        cpa16(sb + A2_TILE * 4 + 16,  klg + (size_t)k0 * kstep + 4);
        cpa16(sb + A2_TILE * 8,       vhg + k0 / 2);
        cpa16(sb + A2_TILE * 8 + 16,  vhg + k0 / 2 + 4);
        cpa16(sb + A2_TILE * 12,      vlg + k0 / 2);
        cpa16(sb + A2_TILE * 12 + 16, vlg + k0 / 2 + 4);
        if (tid < 4)
            cpa16(smbase + (A2_MSK + st * 16) * 4 + tid * 16,
                  kpm + (size_t)b * S_LEN + k0 + tid * 16);
    };

    const int ktiles = 2 * qt + 2;

    load_tile(0, 0);
    CP_COMMIT();
    load_tile(1, 1);
    CP_COMMIT();

    for (int kt = 0; kt < ktiles; kt++) {
        const int k0 = kt * 64;
        if (kt + 1 < ktiles) CP_WAIT1(); else CP_WAIT0();
        __syncthreads();

        const uint32_t* St  = su + (kt & 1) * A2_STAGE;
        const uint32_t* Ksh = St;
        const uint32_t* Ksl = St + A2_TILE;
        const uint32_t* Vsh = St + 2 * A2_TILE;
        const uint32_t* Vsl = St + 3 * A2_TILE;
        const unsigned char* mb = (const unsigned char*)(su + A2_MSK + (kt & 1) * 16);

        float sc[8][4];
        #pragma unroll
        for (int nt = 0; nt < 8; nt++)
            #pragma unroll
            for (int i = 0; i < 4; i++) sc[nt][i] = 0.0f;

        #pragma unroll
        for (int kc = 0; kc < 4; kc++) {
            uint32_t bh[8][2], bl[8][2];
            #pragma unroll
            for (int nt = 0; nt < 8; nt++) {
                const int kr = (nt * 8 + gi) * A2_LDK + kc * 8 + t4;
                bh[nt][0] = Ksh[kr];
                bh[nt][1] = Ksh[kr + 4];
                bl[nt][0] = Ksl[kr];
                bl[nt][1] = Ksl[kr + 4];
            }
            #pragma unroll
            for (int nt = 0; nt < 8; nt++) mma_bf16(sc[nt], ql[kc], bh[nt][0], bh[nt][1]);
            #pragma unroll
            for (int nt = 0; nt < 8; nt++) mma_bf16(sc[nt], qh[kc], bl[nt][0], bl[nt][1]);
            #pragma unroll
            for (int nt = 0; nt < 8; nt++) mma_bf16(sc[nt], qh[kc], bh[nt][0], bh[nt][1]);
        }

        const bool needc = (k0 + 63) > row0;
        float rm0 = NEG, rm1 = NEG;
        #pragma unroll
        for (int nt = 0; nt < 8; nt++) {
            const int col = k0 + nt * 8 + 2 * t4;
            const float mg0 = mb[nt * 8 + 2 * t4]     ? NEG : 0.0f;
            const float mg1 = mb[nt * 8 + 2 * t4 + 1] ? NEG : 0.0f;
            float v0 = sc[nt][0] * scale + mg0;
            float v1 = sc[nt][1] * scale + mg1;
            float v2 = sc[nt][2] * scale + mg0;
            float v3 = sc[nt][3] * scale + mg1;
            if (needc) {
                if (col     > row0)     v0 = NEG;
                if (col + 1 > row0)     v1 = NEG;
                if (col     > row0 + 8) v2 = NEG;
                if (col + 1 > row0 + 8) v3 = NEG;
            }
            sc[nt][0] = v0; sc[nt][1] = v1; sc[nt][2] = v2; sc[nt][3] = v3;
            rm0 = fmaxf(rm0, fmaxf(v0, v1));
            rm1 = fmaxf(rm1, fmaxf(v2, v3));
        }
        rm0 = fmaxf(rm0, __shfl_xor_sync(0xffffffffu, rm0, 1, 4));
        rm0 = fmaxf(rm0, __shfl_xor_sync(0xffffffffu, rm0, 2, 4));
        rm1 = fmaxf(rm1, __shfl_xor_sync(0xffffffffu, rm1, 1, 4));
        rm1 = fmaxf(rm1, __shfl_xor_sync(0xffffffffu, rm1, 2, 4));

        const float mn0 = fmaxf(m0, rm0);
        const float mn1 = fmaxf(m1, rm1);
        const float cr0 = __expf(m0 - mn0);
        const float cr1 = __expf(m1 - mn1);

        float ps0 = 0.0f, ps1 = 0.0f;
        #pragma unroll
        for (int nt = 0; nt < 8; nt++) {
            const float e0 = __expf(sc[nt][0] - mn0);
            const float e1 = __expf(sc[nt][1] - mn0);
            const float e2 = __expf(sc[nt][2] - mn1);
            const float e3 = __expf(sc[nt][3] - mn1);
            sc[nt][0] = e0; sc[nt][1] = e1; sc[nt][2] = e2; sc[nt][3] = e3;
            ps0 += e0 + e1;
            ps1 += e2 + e3;
        }
        ps0 += __shfl_xor_sync(0xffffffffu, ps0, 1, 4);
        ps0 += __shfl_xor_sync(0xffffffffu, ps0, 2, 4);
        ps1 += __shfl_xor_sync(0xffffffffu, ps1, 1, 4);
        ps1 += __shfl_xor_sync(0xffffffffu, ps1, 2, 4);

        l0 = l0 * cr0 + ps0;  m0 = mn0;
        l1 = l1 * cr1 + ps1;  m1 = mn1;

        #pragma unroll
        for (int nt = 0; nt < 8; nt++) {
            oc[nt][0] *= cr0; oc[nt][1] *= cr0;
            oc[nt][2] *= cr1; oc[nt][3] *= cr1;
        }

        // ---- O += P V (bf16 x3): P fragments built directly in registers ----
        #pragma unroll
        for (int kc = 0; kc < 4; kc++) {
            uint32_t ah[4], al[4];
            bsplit2(sc[2 * kc][0],     sc[2 * kc][1],     ah[0], al[0]);
            bsplit2(sc[2 * kc][2],     sc[2 * kc][3],     ah[1], al[1]);
            bsplit2(sc[2 * kc + 1][0], sc[2 * kc + 1][1], ah[2], al[2]);
            bsplit2(sc[2 * kc + 1][2], sc[2 * kc + 1][3], ah[3], al[3]);

            uint32_t bh[8][2], bl[8][2];
            #pragma unroll
            for (int nt = 0; nt < 8; nt++) {
                const int vr = (nt * 8 + gi) * A2_LDK + kc * 8 + t4;
                bh[nt][0] = Vsh[vr];
                bh[nt][1] = Vsh[vr + 4];
                bl[nt][0] = Vsl[vr];
                bl[nt][1] = Vsl[vr + 4];
            }
            #pragma unroll
            for (int nt = 0; nt < 8; nt++) mma_bf16(oc[nt], al, bh[nt][0], bh[nt][1]);
            #pragma unroll
            for (int nt = 0; nt < 8; nt++) mma_bf16(oc[nt], ah, bl[nt][0], bl[nt][1]);
            #pragma unroll
            for (int nt = 0; nt < 8; nt++) mma_bf16(oc[nt], ah, bh[nt][0], bh[nt][1]);
        }

        __syncthreads();
        if (kt + 2 < ktiles) {
            load_tile(kt & 1, kt + 2);
            CP_COMMIT();
        }
    }

    const float inv0 = 1.0f / l0;
    const float inv1 = 1.0f / l1;
    uint32_t* o0h = Oh + (size_t)(b * S_LEN + row0) * DU + h * 32;
    uint32_t* o0l = Ol + (size_t)(b * S_LEN + row0) * DU + h * 32;
    uint32_t* o1h = o0h + 8 * DU;
    uint32_t* o1l = o0l + 8 * DU;
    #pragma unroll
    for (int nt = 0; nt < 8; nt++) {
        uint32_t ph, pl;
        bsplit2(oc[nt][0] * inv0, oc[nt][1] * inv0, ph, pl);
        o0h[nt * 4 + t4] = ph;
        o0l[nt * 4 + t4] = pl;
        bsplit2(oc[nt][2] * inv1, oc[nt][3] * inv1, ph, pl);
        o1h[nt * 4 + t4] = ph;
        o1l[nt * 4 + t4] = pl;
    }
}

// ---------------------------------------------------------------------------
// Launch
// ---------------------------------------------------------------------------
extern "C" void kernel_launch(void* const* d_in, const int* in_sizes, int n_in,
                              void* d_out, int out_size)
{
    const float* q    = (const float*)d_in[0];
    const float* k    = (const float*)d_in[1];
    const float* v    = (const float*)d_in[2];
    const unsigned char* kpm = (const unsigned char*)d_in[3];
    const float* Wq = (const float*)d_in[4];
    const float* bq = (const float*)d_in[5];
    const float* Wk = (const float*)d_in[6];
    const float* bk = (const float*)d_in[7];
    const float* Wv = (const float*)d_in[8];
    const float* bv = (const float*)d_in[9];
    const float* Wo = (const float*)d_in[10];
    const float* bo = (const float*)d_in[11];
    float* out = (float*)d_out;

    void *pAh, *pAl, *pWh, *pWl, *pQh, *pQl, *pKh, *pKl, *pVh, *pVl, *pOh, *pOl;
    cudaGetSymbolAddress(&pAh, g_Ahp);
    cudaGetSymbolAddress(&pAl, g_Alp);
    cudaGetSymbolAddress(&pWh, g_Whp);
    cudaGetSymbolAddress(&pWl, g_Wlp);
    cudaGetSymbolAddress(&pQh, g_Qh);
    cudaGetSymbolAddress(&pQl, g_Ql);
    cudaGetSymbolAddress(&pKh, g_Kh);
    cudaGetSymbolAddress(&pKl, g_Kl);
    cudaGetSymbolAddress(&pVh, g_VtH);
    cudaGetSymbolAddress(&pVl, g_VtL);
    cudaGetSymbolAddress(&pOh, g_Oh);
    cudaGetSymbolAddress(&pOl, g_Ol);

    cudaFuncSetAttribute(attn_bf16_kernel,
                         cudaFuncAttributeMaxDynamicSharedMemorySize, A2_SMEM);
    cudaFuncSetAttribute(gemm10_bf16,
                         cudaFuncAttributeMaxDynamicSharedMemorySize, G10_SMEM);

    // 1) pre-split weights + raw q/k/v activations
    dim3 wgrid(DD / 1024, 4);
    split_weights_kernel<<<wgrid, 256>>>(Wq, Wk, Wv, Wo,
                                         (uint32_t*)pWh, (uint32_t*)pWl);
    dim3 sgrid((M_ROWS * D_MODEL) / 1024, 3);
    split_acts_kernel<<<sgrid, 256>>>(q, k, v,
                                      (uint32_t*)pAh, (uint32_t*)pAl);

    // 2) fused Q/K/V projections -> packed (V transposed)
    dim3 ggrid(D_MODEL / 128, M_ROWS / 256, 3);   // (8, 32, 3)
    gemm10_bf16<<<ggrid, 256, G10_SMEM>>>(
        (const uint32_t*)pAh, (const uint32_t*)pAl,
        (const uint32_t*)pWh, (const uint32_t*)pWl,
        bq, bk, bv,
        (uint32_t*)pQh, (uint32_t*)pQl,
        (uint32_t*)pKh, (uint32_t*)pKl,
        (uint32_t*)pVh, (uint32_t*)pVl,
        nullptr, 0, 0);

    // 3) attention -> packed Ao
    dim3 agrid(S_LEN / 128, NH, BATCH);
    attn_bf16_kernel<<<agrid, 256, A2_SMEM>>>(
        (const uint32_t*)pQh, (const uint32_t*)pQl,
        (const uint32_t*)pKh, (const uint32_t*)pKl,
        (const uint32_t*)pVh, (const uint32_t*)pVl,
        kpm,
        (uint32_t*)pOh, (uint32_t*)pOl);

    // 4) output projection (weight slab 3) -> fp32 out
    dim3 ogrid(D_MODEL / 128, M_ROWS / 256, 1);   // (8, 32, 1)
    gemm10_bf16<<<ogrid, 256, G10_SMEM>>>(
        (const uint32_t*)pOh, (const uint32_t*)pOl,
        (const uint32_t*)pWh, (const uint32_t*)pWl,
        bo, bo, bo,
        nullptr, nullptr, nullptr, nullptr, nullptr, nullptr,
        out, 3, 1);
}

// round 17
// speedup vs baseline: 1.4032x; 1.4032x over previous
#include <cuda_runtime.h>
#include <cuda_bf16.h>
#include <cuda_fp16.h>
#include <cstdint>

// Problem constants (fixed by setup_inputs)
#define BATCH   8
#define S_LEN   1024
#define D_MODEL 1024
#define NH      16
#define DH      64
#define M_ROWS  (BATCH * S_LEN)   // 8192
#define DD      (D_MODEL * D_MODEL)
#define DU      (D_MODEL / 2)     // u32 (16-bit pair) per row
#define MU      (M_ROWS * DU)     // u32 per activation slab
#define SU2     (S_LEN / 2)       // key-pairs per sequence

// ---------------------------------------------------------------------------
// Scratch (device globals — no allocations allowed)
// ---------------------------------------------------------------------------
__device__ uint32_t g_Af[3 * MU];            // raw q,k,v single fp16 packed
__device__ uint32_t g_Whf[4 * DD / 2];       // weights fp16 hi
__device__ uint32_t g_Wlf[4 * DD / 2];       // weights fp16 lo
__device__ uint32_t g_Qh[MU], g_Ql[MU];      // projected Q bf16 hi/lo (attn)
__device__ uint32_t g_Kh[MU], g_Kl[MU];      // projected K bf16 hi/lo (attn)
__device__ uint32_t g_VtH[MU], g_VtL[MU];    // projected V transposed bf16 hi/lo
__device__ uint32_t g_Of[MU];                // attn output single fp16 packed

// ---------------------------------------------------------------------------
// fp16 helpers (2-term: a(fp16) * (bh + bl), weights pre-split)
// ---------------------------------------------------------------------------
__device__ __forceinline__ uint32_t hpack(float x0, float x1) {
    __half2 t = __floats2half2_rn(x0, x1);     // x0 -> low half
    return *reinterpret_cast<uint32_t*>(&t);
}
__device__ __forceinline__ void hsplit2(float x0, float x1, uint32_t& ph, uint32_t& pl) {
    const float h0 = __half2float(__float2half_rn(x0));
    const float h1 = __half2float(__float2half_rn(x1));
    ph = hpack(h0, h1);
    pl = hpack(x0 - h0, x1 - h1);
}
__device__ __forceinline__ void mma_f16(float* c, const uint32_t* a, uint32_t b0, uint32_t b1) {
    asm volatile(
        "mma.sync.aligned.m16n8k16.row.col.f32.f16.f16.f32 "
        "{%0,%1,%2,%3}, {%4,%5,%6,%7}, {%8,%9}, {%0,%1,%2,%3};\n"
        : "+f"(c[0]), "+f"(c[1]), "+f"(c[2]), "+f"(c[3])
        : "r"(a[0]), "r"(a[1]), "r"(a[2]), "r"(a[3]), "r"(b0), "r"(b1));
}

// ---------------------------------------------------------------------------
// bf16 helpers (attention kernel — unchanged, measured good)
// ---------------------------------------------------------------------------
__device__ __forceinline__ uint32_t bpack(float x0, float x1) {
    __nv_bfloat162 t = __floats2bfloat162_rn(x0, x1);
    return *reinterpret_cast<uint32_t*>(&t);
}
__device__ __forceinline__ void bsplit2(float x0, float x1, uint32_t& ph, uint32_t& pl) {
    const float h0 = __bfloat162float(__float2bfloat16(x0));
    const float h1 = __bfloat162float(__float2bfloat16(x1));
    ph = bpack(h0, h1);
    pl = bpack(x0 - h0, x1 - h1);
}
__device__ __forceinline__ void mma_bf16(float* c, const uint32_t* a, uint32_t b0, uint32_t b1) {
    asm volatile(
        "mma.sync.aligned.m16n8k16.row.col.f32.bf16.bf16.f32 "
        "{%0,%1,%2,%3}, {%4,%5,%6,%7}, {%8,%9}, {%0,%1,%2,%3};\n"
        : "+f"(c[0]), "+f"(c[1]), "+f"(c[2]), "+f"(c[3])
        : "r"(a[0]), "r"(a[1]), "r"(a[2]), "r"(a[3]), "r"(b0), "r"(b1));
}

// ---------------------------------------------------------------------------
// cp.async helpers
// ---------------------------------------------------------------------------
__device__ __forceinline__ void cpa16(uint32_t smaddr, const void* gptr) {
    asm volatile("cp.async.cg.shared.global [%0], [%1], 16;\n"
                 :: "r"(smaddr), "l"(gptr));
}
#define CP_COMMIT() asm volatile("cp.async.commit_group;\n" ::: "memory")
#define CP_WAIT1()  asm volatile("cp.async.wait_group 1;\n" ::: "memory")
#define CP_WAIT0()  asm volatile("cp.async.wait_group 0;\n" ::: "memory")

// ---------------------------------------------------------------------------
// Pre-split kernels
// ---------------------------------------------------------------------------
__global__ void split_weights_f16(
    const float* __restrict__ W0, const float* __restrict__ W1,
    const float* __restrict__ W2, const float* __restrict__ W3,
    uint32_t* __restrict__ Hp, uint32_t* __restrict__ Lp)
{
    const int z = blockIdx.y;
    const float* W = (z == 0) ? W0 : (z == 1) ? W1 : (z == 2) ? W2 : W3;
    const size_t fi = ((size_t)blockIdx.x * 256 + threadIdx.x) * 4;
    const size_t ui = (size_t)z * (DD / 2) + fi / 2;
    float4 x = *(const float4*)(W + fi);
    uint2 h2, l2;
    hsplit2(x.x, x.y, h2.x, l2.x);
    hsplit2(x.z, x.w, h2.y, l2.y);
    *(uint2*)(Hp + ui) = h2;
    *(uint2*)(Lp + ui) = l2;
}

__global__ void split_acts_f16(
    const float* __restrict__ X0, const float* __restrict__ X1,
    const float* __restrict__ X2,
    uint32_t* __restrict__ P)
{
    const int z = blockIdx.y;
    const float* X = (z == 0) ? X0 : (z == 1) ? X1 : X2;
    const size_t fi = ((size_t)blockIdx.x * 256 + threadIdx.x) * 4;
    const size_t ui = (size_t)z * MU + fi / 2;
    float4 x = *(const float4*)(X + fi);
    uint2 o;
    o.x = hpack(x.x, x.y);
    o.y = hpack(x.z, x.w);
    *(uint2*)(P + ui) = o;
}

// ---------------------------------------------------------------------------
// GEMM v11:  C = A @ W^T + bias.  fp16 2-term: A single fp16,
// W pre-split fp16 hi+lo; per (mt,nt,k16): mma(a,bl) + mma(a,bh).
// 128x128x32 CTA tile, 256 threads, cp.async 2-stage, stride-20 smem
// (conflict-free, proven). 40 LDS + 32 mma per k16 (was 48+48).
// Epilogues unchanged from gemm9 (bf16 hi/lo packed Q/K/Vt, fp32 outproj).
// ---------------------------------------------------------------------------
#define GBK 32
#define GKU 16
#define GLD 20
#define TILE_U32 (128 * GLD)
#define STAGE_U32 (3 * TILE_U32)
#define G11_SMEM (2 * STAGE_U32 * 4)   // 61440 bytes

__global__ void __launch_bounds__(256, 2) gemm11_f16(
    const uint32_t* __restrict__ Afp,
    const uint32_t* __restrict__ Whp, const uint32_t* __restrict__ Wlp,
    const float* __restrict__ b0, const float* __restrict__ b1, const float* __restrict__ b2,
    uint32_t* __restrict__ QhO, uint32_t* __restrict__ QlO,
    uint32_t* __restrict__ KhO, uint32_t* __restrict__ KlO,
    uint32_t* __restrict__ VtHO, uint32_t* __restrict__ VtLO,
    float* __restrict__ Cout,
    int widx0, int outproj)
{
    extern __shared__ uint32_t smu[];

    const int z = blockIdx.z;
    const float* bias = (z == 0) ? b0 : (z == 1) ? b1 : b2;
    const uint32_t* Af = Afp + (size_t)z * MU;
    const uint32_t* Bh = Whp + (size_t)(widx0 + z) * (DD / 2);
    const uint32_t* Bl = Wlp + (size_t)(widx0 + z) * (DD / 2);

    const int tid  = threadIdx.x;
    const int lane = tid & 31;
    const int warp = tid >> 5;
    const int wm = warp & 3;
    const int wn = warp >> 2;
    const int gi = lane >> 2;
    const int t4 = lane & 3;

    const int bm = blockIdx.y * 128;
    const int bn = blockIdx.x * 128;

    const int lr = tid >> 1;
    const int uc = (tid & 1) * 8;
    const uint32_t* Ag  = Af + (size_t)(bm + lr) * DU + uc;
    const uint32_t* Bhg = Bh + (size_t)(bn + lr) * DU + uc;
    const uint32_t* Blg = Bl + (size_t)(bn + lr) * DU + uc;

    const uint32_t smbase = (uint32_t)__cvta_generic_to_shared(smu);
    const uint32_t rowoff = (lr * GLD + uc) * 4;

    float acc[2][8][4];
    #pragma unroll
    for (int mt = 0; mt < 2; mt++)
        #pragma unroll
        for (int nt = 0; nt < 8; nt++)
            #pragma unroll
            for (int i = 0; i < 4; i++) acc[mt][nt][i] = 0.0f;

    auto load_stage = [&](int st, int k0) {
        const int ku = k0 >> 1;
        const uint32_t sb = smbase + (uint32_t)st * (STAGE_U32 * 4) + rowoff;
        cpa16(sb,                     Ag + ku);
        cpa16(sb + 16,                Ag + ku + 4);
        cpa16(sb + TILE_U32 * 4,      Bhg + ku);
        cpa16(sb + TILE_U32 * 4 + 16, Bhg + ku + 4);
        cpa16(sb + TILE_U32 * 8,      Blg + ku);
        cpa16(sb + TILE_U32 * 8 + 16, Blg + ku + 4);
    };

    const int ntiles = D_MODEL / GBK;
    load_stage(0, 0);
    CP_COMMIT();
    load_stage(1, GBK);
    CP_COMMIT();

    for (int i = 0; i < ntiles; i++) {
        if (i + 1 < ntiles) CP_WAIT1(); else CP_WAIT0();
        __syncthreads();

        const uint32_t* S   = smu + (i & 1) * STAGE_U32;
        const uint32_t* Sa  = S;
        const uint32_t* Sbh = S + TILE_U32;
        const uint32_t* Sbl = S + 2 * TILE_U32;

        #pragma unroll
        for (int kk = 0; kk < GKU; kk += 8) {
            uint32_t af[2][4];
            #pragma unroll
            for (int mt = 0; mt < 2; mt++) {
                const int r = wm * 32 + mt * 16 + gi;
                af[mt][0] = Sa[r * GLD + kk + t4];
                af[mt][1] = Sa[(r + 8) * GLD + kk + t4];
                af[mt][2] = Sa[r * GLD + kk + t4 + 4];
                af[mt][3] = Sa[(r + 8) * GLD + kk + t4 + 4];
            }
            #pragma unroll
            for (int nt = 0; nt < 8; nt++) {
                const int rb = wn * 64 + nt * 8 + gi;
                const uint32_t bh0 = Sbh[rb * GLD + kk + t4];
                const uint32_t bh1 = Sbh[rb * GLD + kk + t4 + 4];
                const uint32_t bl0 = Sbl[rb * GLD + kk + t4];
                const uint32_t bl1 = Sbl[rb * GLD + kk + t4 + 4];
                #pragma unroll
                for (int mt = 0; mt < 2; mt++) {
                    mma_f16(acc[mt][nt], af[mt], bl0, bl1);
                    mma_f16(acc[mt][nt], af[mt], bh0, bh1);
                }
            }
        }

        __syncthreads();
        if (i + 2 < ntiles) {
            load_stage(i & 1, (i + 2) * GBK);
            CP_COMMIT();
        }
    }

    // ---------------- epilogue ----------------
    if (outproj) {
        #pragma unroll
        for (int nt = 0; nt < 8; nt++) {
            const int col = bn + wn * 64 + nt * 8 + 2 * t4;
            const float2 bb = *(const float2*)(bias + col);
            #pragma unroll
            for (int mt = 0; mt < 2; mt++) {
                const int row0 = bm + wm * 32 + mt * 16 + gi;
                float2 o0, o1;
                o0.x = acc[mt][nt][0] + bb.x; o0.y = acc[mt][nt][1] + bb.y;
                o1.x = acc[mt][nt][2] + bb.x; o1.y = acc[mt][nt][3] + bb.y;
                *(float2*)(Cout + (size_t)row0 * D_MODEL + col)       = o0;
                *(float2*)(Cout + (size_t)(row0 + 8) * D_MODEL + col) = o1;
            }
        }
    } else if (z < 2) {
        uint32_t* Ho = (z == 0) ? QhO : KhO;
        uint32_t* Lo = (z == 0) ? QlO : KlO;
        #pragma unroll
        for (int nt = 0; nt < 8; nt++) {
            const int col  = bn + wn * 64 + nt * 8 + 2 * t4;
            const int colu = col >> 1;
            const float2 bb = *(const float2*)(bias + col);
            #pragma unroll
            for (int mt = 0; mt < 2; mt++) {
                const int row0 = bm + wm * 32 + mt * 16 + gi;
                uint32_t ph, pl;
                bsplit2(acc[mt][nt][0] + bb.x, acc[mt][nt][1] + bb.y, ph, pl);
                Ho[(size_t)row0 * DU + colu] = ph;
                Lo[(size_t)row0 * DU + colu] = pl;
                bsplit2(acc[mt][nt][2] + bb.x, acc[mt][nt][3] + bb.y, ph, pl);
                Ho[(size_t)(row0 + 8) * DU + colu] = ph;
                Lo[(size_t)(row0 + 8) * DU + colu] = pl;
            }
        }
    } else {
        // V: transposed packed per (b,h): [dh][key-pair]
        #pragma unroll
        for (int nt = 0; nt < 8; nt++) {
            const int cg = bn + wn * 64 + nt * 8 + 2 * t4;
            const float2 bb = *(const float2*)(bias + cg);
            #pragma unroll
            for (int mt = 0; mt < 2; mt++) {
                const int r = bm + wm * 32 + mt * 16 + gi;
                const float c0 = acc[mt][nt][0] + bb.x;
                const float c1 = acc[mt][nt][1] + bb.y;
                const float c2 = acc[mt][nt][2] + bb.x;
                const float c3 = acc[mt][nt][3] + bb.y;
                const float p0 = __shfl_xor_sync(0xffffffffu, c0, 4);
                const float p1 = __shfl_xor_sync(0xffffffffu, c1, 4);
                const float p2 = __shfl_xor_sync(0xffffffffu, c2, 4);
                const float p3 = __shfl_xor_sync(0xffffffffu, c3, 4);
                uint32_t ph, pl;
                if ((gi & 1) == 0) {
                    const int bb_ = r >> 10, s = r & 1023;
                    const int h_ = cg >> 6, dh = cg & 63;
                    const size_t plane = ((size_t)(bb_ * NH + h_) * DH + dh) * SU2;
                    bsplit2(c0, p0, ph, pl);
                    VtHO[plane + (s >> 1)] = ph;
                    VtLO[plane + (s >> 1)] = pl;
                    bsplit2(c2, p2, ph, pl);
                    VtHO[plane + (s >> 1) + 4] = ph;
                    VtLO[plane + (s >> 1) + 4] = pl;
                } else {
                    const int rr = r - 1;
                    const int bb_ = rr >> 10, s = rr & 1023;
                    const int h_ = (cg + 1) >> 6, dh = (cg + 1) & 63;
                    const size_t plane = ((size_t)(bb_ * NH + h_) * DH + dh) * SU2;
                    bsplit2(p1, c1, ph, pl);
                    VtHO[plane + (s >> 1)] = ph;
                    VtLO[plane + (s >> 1)] = pl;
                    bsplit2(p3, c3, ph, pl);
                    VtHO[plane + (s >> 1) + 4] = ph;
                    VtLO[plane + (s >> 1) + 4] = pl;
                }
            }
        }
    }
}

// ---------------------------------------------------------------------------
// Flash attention (round-15 exact, measured 248us): bf16x3, pre-packed
// operands, cp.async 2-stage, register-direct P fragments.
// Only change: final store writes SINGLE fp16 packed Ao for the out-proj.
// ---------------------------------------------------------------------------
#define A2_LDK 36
#define A2_TILE (64 * A2_LDK)
#define A2_STAGE (4 * A2_TILE)
#define A2_MSK (2 * A2_STAGE)
#define A2_SMEM ((A2_MSK + 32) * 4)

__global__ void __launch_bounds__(256, 1) attn_bf16_kernel(
    const uint32_t* __restrict__ Qh, const uint32_t* __restrict__ Ql,
    const uint32_t* __restrict__ Kh, const uint32_t* __restrict__ Kl,
    const uint32_t* __restrict__ VtH, const uint32_t* __restrict__ VtL,
    const unsigned char* __restrict__ kpm,
    uint32_t* __restrict__ Of)
{
    extern __shared__ uint32_t su[];

    const int b   = blockIdx.z;
    const int h   = blockIdx.y;
    const int qt  = gridDim.x - 1 - blockIdx.x;   // heavy tiles first
    const int tid = threadIdx.x;
    const int w    = tid >> 5;
    const int lane = tid & 31;
    const int gi = lane >> 2;
    const int t4 = lane & 3;

    const int q0   = qt * 128;
    const int row0 = q0 + w * 16 + gi;

    const float scale = 0.125f;
    const float NEG = -1e30f;

    uint32_t qh[4][4], ql[4][4];
    {
        const uint32_t* q0h = Qh + (size_t)(b * S_LEN + row0) * DU + h * 32;
        const uint32_t* q1h = q0h + 8 * DU;
        const uint32_t* q0l = Ql + (size_t)(b * S_LEN + row0) * DU + h * 32;
        const uint32_t* q1l = q0l + 8 * DU;
        #pragma unroll
        for (int kc = 0; kc < 4; kc++) {
            qh[kc][0] = q0h[kc * 8 + t4];
            qh[kc][1] = q1h[kc * 8 + t4];
            qh[kc][2] = q0h[kc * 8 + t4 + 4];
            qh[kc][3] = q1h[kc * 8 + t4 + 4];
            ql[kc][0] = q0l[kc * 8 + t4];
            ql[kc][1] = q1l[kc * 8 + t4];
            ql[kc][2] = q0l[kc * 8 + t4 + 4];
            ql[kc][3] = q1l[kc * 8 + t4 + 4];
        }
    }

    float oc[8][4];
    #pragma unroll
    for (int nt = 0; nt < 8; nt++)
        #pragma unroll
        for (int i = 0; i < 4; i++) oc[nt][i] = 0.0f;
    float m0 = NEG, m1 = NEG, l0 = 0.0f, l1 = 0.0f;

    const int ldr = tid >> 2;
    const int seg = tid & 3;
    const uint32_t smbase = (uint32_t)__cvta_generic_to_shared(su);
    const uint32_t dsto = (uint32_t)(ldr * A2_LDK + seg * 8) * 4;

    const uint32_t* khg = Kh + (size_t)(b * S_LEN + ldr) * DU + h * 32 + seg * 8;
    const uint32_t* klg = Kl + (size_t)(b * S_LEN + ldr) * DU + h * 32 + seg * 8;
    const uint32_t* vhg = VtH + ((size_t)(b * NH + h) * DH + ldr) * SU2 + seg * 8;
    const uint32_t* vlg = VtL + ((size_t)(b * NH + h) * DH + ldr) * SU2 + seg * 8;
    const size_t kstep = (size_t)DU;

    auto load_tile = [&](int st, int kt) {
        const int k0 = kt * 64;
        const uint32_t sb = smbase + (uint32_t)st * (A2_STAGE * 4) + dsto;
        cpa16(sb,                     khg + (size_t)k0 * kstep);
        cpa16(sb + 16,                khg + (size_t)k0 * kstep + 4);
        cpa16(sb + A2_TILE * 4,       klg + (size_t)k0 * kstep);
        cpa16(sb + A2_TILE * 4 + 16,  klg + (size_t)k0 * kstep + 4);
        cpa16(sb + A2_TILE * 8,       vhg + k0 / 2);
        cpa16(sb + A2_TILE * 8 + 16,  vhg + k0 / 2 + 4);
        cpa16(sb + A2_TILE * 12,      vlg + k0 / 2);
        cpa16(sb + A2_TILE * 12 + 16, vlg + k0 / 2 + 4);
        if (tid < 4)
            cpa16(smbase + (A2_MSK + st * 16) * 4 + tid * 16,
                  kpm + (size_t)b * S_LEN + k0 + tid * 16);
    };

    const int ktiles = 2 * qt + 2;

    load_tile(0, 0);
    CP_COMMIT();
    load_tile(1, 1);
    CP_COMMIT();

    for (int kt = 0; kt < ktiles; kt++) {
        const int k0 = kt * 64;
        if (kt + 1 < ktiles) CP_WAIT1(); else CP_WAIT0();
        __syncthreads();

        const uint32_t* St  = su + (kt & 1) * A2_STAGE;
        const uint32_t* Ksh = St;
        const uint32_t* Ksl = St + A2_TILE;
        const uint32_t* Vsh = St + 2 * A2_TILE;
        const uint32_t* Vsl = St + 3 * A2_TILE;
        const unsigned char* mb = (const unsigned char*)(su + A2_MSK + (kt & 1) * 16);

        float sc[8][4];
        #pragma unroll
        for (int nt = 0; nt < 8; nt++)
            #pragma unroll
            for (int i = 0; i < 4; i++) sc[nt][i] = 0.0f;

        #pragma unroll
        for (int kc = 0; kc < 4; kc++) {
            uint32_t bh[8][2], bl[8][2];
            #pragma unroll
            for (int nt = 0; nt < 8; nt++) {
                const int kr = (nt * 8 + gi) * A2_LDK + kc * 8 + t4;
                bh[nt][0] = Ksh[kr];
                bh[nt][1] = Ksh[kr + 4];
                bl[nt][0] = Ksl[kr];
                bl[nt][1] = Ksl[kr + 4];
            }
            #pragma unroll
            for (int nt = 0; nt < 8; nt++) mma_bf16(sc[nt], ql[kc], bh[nt][0], bh[nt][1]);
            #pragma unroll
            for (int nt = 0; nt < 8; nt++) mma_bf16(sc[nt], qh[kc], bl[nt][0], bl[nt][1]);
            #pragma unroll
            for (int nt = 0; nt < 8; nt++) mma_bf16(sc[nt], qh[kc], bh[nt][0], bh[nt][1]);
        }

        const bool needc = (k0 + 63) > row0;
        float rm0 = NEG, rm1 = NEG;
        #pragma unroll
        for (int nt = 0; nt < 8; nt++) {
            const int col = k0 + nt * 8 + 2 * t4;
            const float mg0 = mb[nt * 8 + 2 * t4]     ? NEG : 0.0f;
            const float mg1 = mb[nt * 8 + 2 * t4 + 1] ? NEG : 0.0f;
            float v0 = sc[nt][0] * scale + mg0;
            float v1 = sc[nt][1] * scale + mg1;
            float v2 = sc[nt][2] * scale + mg0;
            float v3 = sc[nt][3] * scale + mg1;
            if (needc) {
                if (col     > row0)     v0 = NEG;
                if (col + 1 > row0)     v1 = NEG;
                if (col     > row0 + 8) v2 = NEG;
                if (col + 1 > row0 + 8) v3 = NEG;
            }
            sc[nt][0] = v0; sc[nt][1] = v1; sc[nt][2] = v2; sc[nt][3] = v3;
            rm0 = fmaxf(rm0, fmaxf(v0, v1));
            rm1 = fmaxf(rm1, fmaxf(v2, v3));
        }
        rm0 = fmaxf(rm0, __shfl_xor_sync(0xffffffffu, rm0, 1, 4));
        rm0 = fmaxf(rm0, __shfl_xor_sync(0xffffffffu, rm0, 2, 4));
        rm1 = fmaxf(rm1, __shfl_xor_sync(0xffffffffu, rm1, 1, 4));
        rm1 = fmaxf(rm1, __shfl_xor_sync(0xffffffffu, rm1, 2, 4));

        const float mn0 = fmaxf(m0, rm0);
        const float mn1 = fmaxf(m1, rm1);
        const float cr0 = __expf(m0 - mn0);
        const float cr1 = __expf(m1 - mn1);

        float ps0 = 0.0f, ps1 = 0.0f;
        #pragma unroll
        for (int nt = 0; nt < 8; nt++) {
            const float e0 = __expf(sc[nt][0] - mn0);
            const float e1 = __expf(sc[nt][1] - mn0);
            const float e2 = __expf(sc[nt][2] - mn1);
            const float e3 = __expf(sc[nt][3] - mn1);
            sc[nt][0] = e0; sc[nt][1] = e1; sc[nt][2] = e2; sc[nt][3] = e3;
            ps0 += e0 + e1;
            ps1 += e2 + e3;
        }
        ps0 += __shfl_xor_sync(0xffffffffu, ps0, 1, 4);
        ps0 += __shfl_xor_sync(0xffffffffu, ps0, 2, 4);
        ps1 += __shfl_xor_sync(0xffffffffu, ps1, 1, 4);
        ps1 += __shfl_xor_sync(0xffffffffu, ps1, 2, 4);

        l0 = l0 * cr0 + ps0;  m0 = mn0;
        l1 = l1 * cr1 + ps1;  m1 = mn1;

        #pragma unroll
        for (int nt = 0; nt < 8; nt++) {
            oc[nt][0] *= cr0; oc[nt][1] *= cr0;
            oc[nt][2] *= cr1; oc[nt][3] *= cr1;
        }

        // ---- O += P V (bf16 x3): P fragments built directly in registers ----
        #pragma unroll
        for (int kc = 0; kc < 4; kc++) {
            uint32_t ah[4], al[4];
            bsplit2(sc[2 * kc][0],     sc[2 * kc][1],     ah[0], al[0]);
            bsplit2(sc[2 * kc][2],     sc[2 * kc][3],     ah[1], al[1]);
            bsplit2(sc[2 * kc + 1][0], sc[2 * kc + 1][1], ah[2], al[2]);
            bsplit2(sc[2 * kc + 1][2], sc[2 * kc + 1][3], ah[3], al[3]);

            uint32_t bh[8][2], bl[8][2];
            #pragma unroll
            for (int nt = 0; nt < 8; nt++) {
                const int vr = (nt * 8 + gi) * A2_LDK + kc * 8 + t4;
                bh[nt][0] = Vsh[vr];
                bh[nt][1] = Vsh[vr + 4];
                bl[nt][0] = Vsl[vr];
                bl[nt][1] = Vsl[vr + 4];
            }
            #pragma unroll
            for (int nt = 0; nt < 8; nt++) mma_bf16(oc[nt], al, bh[nt][0], bh[nt][1]);
            #pragma unroll
            for (int nt = 0; nt < 8; nt++) mma_bf16(oc[nt], ah, bl[nt][0], bl[nt][1]);
            #pragma unroll
            for (int nt = 0; nt < 8; nt++) mma_bf16(oc[nt], ah, bh[nt][0], bh[nt][1]);
        }

        __syncthreads();
        if (kt + 2 < ktiles) {
            load_tile(kt & 1, kt + 2);
            CP_COMMIT();
        }
    }

    // ---- normalize + store SINGLE fp16 packed (out-proj input) ----
    const float inv0 = 1.0f / l0;
    const float inv1 = 1.0f / l1;
    uint32_t* o0 = Of + (size_t)(b * S_LEN + row0) * DU + h * 32;
    uint32_t* o1 = o0 + 8 * DU;
    #pragma unroll
    for (int nt = 0; nt < 8; nt++) {
        o0[nt * 4 + t4] = hpack(oc[nt][0] * inv0, oc[nt][1] * inv0);
        o1[nt * 4 + t4] = hpack(oc[nt][2] * inv1, oc[nt][3] * inv1);
    }
}

// ---------------------------------------------------------------------------
// Launch
// ---------------------------------------------------------------------------
extern "C" void kernel_launch(void* const* d_in, const int* in_sizes, int n_in,
                              void* d_out, int out_size)
{
    const float* q    = (const float*)d_in[0];
    const float* k    = (const float*)d_in[1];
    const float* v    = (const float*)d_in[2];
    const unsigned char* kpm = (const unsigned char*)d_in[3];
    const float* Wq = (const float*)d_in[4];
    const float* bq = (const float*)d_in[5];
    const float* Wk = (const float*)d_in[6];
    const float* bk = (const float*)d_in[7];
    const float* Wv = (const float*)d_in[8];
    const float* bv = (const float*)d_in[9];
    const float* Wo = (const float*)d_in[10];
    const float* bo = (const float*)d_in[11];
    float* out = (float*)d_out;

    void *pAf, *pWh, *pWl, *pQh, *pQl, *pKh, *pKl, *pVh, *pVl, *pOf;
    cudaGetSymbolAddress(&pAf, g_Af);
    cudaGetSymbolAddress(&pWh, g_Whf);
    cudaGetSymbolAddress(&pWl, g_Wlf);
    cudaGetSymbolAddress(&pQh, g_Qh);
    cudaGetSymbolAddress(&pQl, g_Ql);
    cudaGetSymbolAddress(&pKh, g_Kh);
    cudaGetSymbolAddress(&pKl, g_Kl);
    cudaGetSymbolAddress(&pVh, g_VtH);
    cudaGetSymbolAddress(&pVl, g_VtL);
    cudaGetSymbolAddress(&pOf, g_Of);

    cudaFuncSetAttribute(attn_bf16_kernel,
                         cudaFuncAttributeMaxDynamicSharedMemorySize, A2_SMEM);
    cudaFuncSetAttribute(gemm11_f16,
                         cudaFuncAttributeMaxDynamicSharedMemorySize, G11_SMEM);

    // 1) pre-split weights (fp16 hi/lo) + raw q/k/v (single fp16)
    dim3 wgrid(DD / 1024, 4);
    split_weights_f16<<<wgrid, 256>>>(Wq, Wk, Wv, Wo,
                                      (uint32_t*)pWh, (uint32_t*)pWl);
    dim3 sgrid((M_ROWS * D_MODEL) / 1024, 3);
    split_acts_f16<<<sgrid, 256>>>(q, k, v, (uint32_t*)pAf);

    // 2) fused Q/K/V projections (fp16 2-term) -> bf16 packed (V transposed)
    dim3 ggrid(D_MODEL / 128, M_ROWS / 128, 3);
    gemm11_f16<<<ggrid, 256, G11_SMEM>>>(
        (const uint32_t*)pAf,
        (const uint32_t*)pWh, (const uint32_t*)pWl,
        bq, bk, bv,
        (uint32_t*)pQh, (uint32_t*)pQl,
        (uint32_t*)pKh, (uint32_t*)pKl,
        (uint32_t*)pVh, (uint32_t*)pVl,
        nullptr, 0, 0);

    // 3) attention (bf16 x3, unchanged) -> single fp16 Ao
    dim3 agrid(S_LEN / 128, NH, BATCH);
    attn_bf16_kernel<<<agrid, 256, A2_SMEM>>>(
        (const uint32_t*)pQh, (const uint32_t*)pQl,
        (const uint32_t*)pKh, (const uint32_t*)pKl,
        (const uint32_t*)pVh, (const uint32_t*)pVl,
        kpm,
        (uint32_t*)pOf);

    // 4) output projection (fp16 2-term, weight slab 3) -> fp32 out
    dim3 ogrid(D_MODEL / 128, M_ROWS / 128, 1);
    gemm11_f16<<<ogrid, 256, G11_SMEM>>>(
        (const uint32_t*)pOf,
        (const uint32_t*)pWh, (const uint32_t*)pWl,
        bo, bo, bo,
        nullptr, nullptr, nullptr, nullptr, nullptr, nullptr,
        out, 3, 1);
}